// round 10
// baseline (speedup 1.0000x reference)
#include <cuda_runtime.h>
#include <cuda_bf16.h>
#include <cstdint>

// ---------------- problem constants ----------------
#define BB    2048
#define F1N   10
#define F2N   25
#define NTOK  261
#define D4    32
#define GRP   12                 // rows per batch group (h0 + 10*h1 + 1 dummy)
#define MPAD  (BB * GRP)         // 24576 padded GEMM1 rows

// ---------------- scratch (device globals, allocation-free) ----------------
__device__ __align__(16) __nv_bfloat16 g_Ah[MPAD * 256];
__device__ __align__(16) __nv_bfloat16 g_Al[MPAD * 256];
__device__ __align__(16) __nv_bfloat16 g_A2h[BB * 512];
__device__ __align__(16) __nv_bfloat16 g_A2l[BB * 512];
__device__ __align__(16) __nv_bfloat16 g_W1hT[256 * 256];
__device__ __align__(16) __nv_bfloat16 g_W1lT[256 * 256];
__device__ __align__(16) __nv_bfloat16 g_W2hT[256 * 512];
__device__ __align__(16) __nv_bfloat16 g_W2lT[256 * 512];

// ---------------- PTX helpers (base sm_100-safe) ----------------
__device__ __forceinline__ uint32_t smem_u32(const void* p) {
    uint32_t a;
    asm("{ .reg .u64 t; cvta.to.shared.u64 t, %1; cvt.u32.u64 %0, t; }" : "=r"(a) : "l"(p));
    return a;
}
__device__ __forceinline__ void cp16(uint32_t s, const void* g) {
    asm volatile("cp.async.cg.shared.global [%0], [%1], 16;" :: "r"(s), "l"(g));
}
#define CP_COMMIT() asm volatile("cp.async.commit_group;" ::: "memory")
#define CP_WAIT(n)  asm volatile("cp.async.wait_group %0;" :: "n"(n) : "memory")

__device__ __forceinline__ void ldsm4(uint32_t* r, uint32_t addr) {
    asm volatile("ldmatrix.sync.aligned.m8n8.x4.shared.b16 {%0,%1,%2,%3}, [%4];"
                 : "=r"(r[0]), "=r"(r[1]), "=r"(r[2]), "=r"(r[3]) : "r"(addr));
}
__device__ __forceinline__ void mma16816(float* c, const uint32_t* a, const uint32_t* b) {
    asm volatile(
        "mma.sync.aligned.m16n8k16.row.col.f32.bf16.bf16.f32 "
        "{%0,%1,%2,%3}, {%4,%5,%6,%7}, {%8,%9}, {%0,%1,%2,%3};"
        : "+f"(c[0]), "+f"(c[1]), "+f"(c[2]), "+f"(c[3])
        : "r"(a[0]), "r"(a[1]), "r"(a[2]), "r"(a[3]), "r"(b[0]), "r"(b[1]));
}

// ---------------- bf16 split helpers ----------------
__device__ __forceinline__ void split1(float w, unsigned short& h, unsigned short& l) {
    __nv_bfloat16 hb = __float2bfloat16_rn(w);
    float r = w - __bfloat162float(hb);
    __nv_bfloat16 lb = __float2bfloat16_rn(r);
    h = __bfloat16_as_ushort(hb);
    l = __bfloat16_as_ushort(lb);
}
__device__ __forceinline__ void split_store2(__nv_bfloat16* H, __nv_bfloat16* L,
                                             size_t idx, float a, float b) {
    unsigned short h0, l0, h1, l1;
    split1(a, h0, l0);
    split1(b, h1, l1);
    *reinterpret_cast<uint32_t*>(H + idx) = (uint32_t)h0 | ((uint32_t)h1 << 16);
    *reinterpret_cast<uint32_t*>(L + idx) = (uint32_t)l0 | ((uint32_t)l1 << 16);
}
__device__ __forceinline__ void split_store4(__nv_bfloat16* H, __nv_bfloat16* L,
                                             size_t idx, float4 v) {
    unsigned short hs[4], ls[4];
    float f[4] = {v.x, v.y, v.z, v.w};
#pragma unroll
    for (int i = 0; i < 4; i++) split1(f[i], hs[i], ls[i]);
    *reinterpret_cast<uint2*>(H + idx) =
        make_uint2((uint32_t)hs[0] | ((uint32_t)hs[1] << 16),
                   (uint32_t)hs[2] | ((uint32_t)hs[3] << 16));
    *reinterpret_cast<uint2*>(L + idx) =
        make_uint2((uint32_t)ls[0] | ((uint32_t)ls[1] << 16),
                   (uint32_t)ls[2] | ((uint32_t)ls[3] << 16));
}

// ---------------- K1: merged weight-prep + neighbor-mean reduce (at HBM floor) ----------------
#define CONVW_BLOCKS 192
__global__ __launch_bounds__(256)
void k_prep(const float4* __restrict__ x4,
            const float* __restrict__ W1, const float* __restrict__ W2) {
    __shared__ float tile[32][33];
    if (blockIdx.x < CONVW_BLOCKS) {
        int t = blockIdx.x;
        const float* W;
        __nv_bfloat16 *OH, *OL;
        int KD, ND, tk, tn;
        if (t < 64) {
            W = W1; OH = g_W1hT; OL = g_W1lT; KD = 256; ND = 256;
            tk = t >> 3; tn = t & 7;
        } else {
            t -= 64;
            W = W2; OH = g_W2hT; OL = g_W2lT; KD = 512; ND = 256;
            tk = t >> 3; tn = t & 7;
        }
        int x = threadIdx.x & 31, y0 = threadIdx.x >> 5;
#pragma unroll
        for (int yy = 0; yy < 4; yy++) {
            int k = tk * 32 + y0 * 4 + yy;
            tile[y0 * 4 + yy][x] = W[(size_t)k * ND + tn * 32 + x];
        }
        __syncthreads();
#pragma unroll
        for (int yy = 0; yy < 4; yy++) {
            int n = tn * 32 + y0 * 4 + yy;
            float v = tile[x][y0 * 4 + yy];
            unsigned short h, l;
            split1(v, h, l);
            size_t o = (size_t)n * KD + tk * 32 + x;
            OH[o] = __ushort_as_bfloat16(h);
            OL[o] = __ushort_as_bfloat16(l);
        }
        return;
    }

    const int HOP2_SLOTS = BB * F1N * D4;  // 655360
    int idx = (blockIdx.x - CONVW_BLOCKS) * blockDim.x + threadIdx.x;
    if (idx < HOP2_SLOTS) {
        int d4 = idx & 31;
        int fg = idx >> 5;
        int f = fg % F1N;
        int b = fg / F1N;
        const float4* p = x4 + (size_t)b * NTOK * D4 + (size_t)(1 + F1N + f * F2N) * D4 + d4;
        float4 s[5];
#pragma unroll
        for (int j = 0; j < 5; j++) s[j] = make_float4(0.f, 0.f, 0.f, 0.f);
#pragma unroll
        for (int kb = 0; kb < 5; kb++) {
#pragma unroll
            for (int j = 0; j < 5; j++) {
                float4 v = p[(size_t)(kb * 5 + j) * D4];
                s[j].x += v.x; s[j].y += v.y; s[j].z += v.z; s[j].w += v.w;
            }
        }
        float4 tot = make_float4(
            s[0].x + s[1].x + s[2].x + s[3].x + s[4].x,
            s[0].y + s[1].y + s[2].y + s[3].y + s[4].y,
            s[0].z + s[1].z + s[2].z + s[3].z + s[4].z,
            s[0].w + s[1].w + s[2].w + s[3].w + s[4].w);
        const float inv = 1.0f / (float)F2N;
        size_t row = (size_t)b * GRP + 1 + f;
        split_store4(g_Ah, g_Al, row * 256 + 128 + d4 * 4,
                     make_float4(tot.x * inv, tot.y * inv, tot.z * inv, tot.w * inv));
    } else {
        int j = idx - HOP2_SLOTS;
        if (j >= BB * D4) return;
        int d4 = j & 31;
        int b = j >> 5;
        const float4* p = x4 + (size_t)b * NTOK * D4;
        size_t base = (size_t)b * GRP;
        split_store4(g_Ah, g_Al, base * 256 + d4 * 4, p[d4]);  // seed
        float4 s0 = make_float4(0.f, 0.f, 0.f, 0.f), s1 = s0;
#pragma unroll
        for (int f = 0; f < F1N; f += 2) {
            float4 v0 = p[(size_t)(1 + f) * D4 + d4];
            float4 v1 = p[(size_t)(2 + f) * D4 + d4];
            split_store4(g_Ah, g_Al, (base + 1 + f) * 256 + d4 * 4, v0);
            split_store4(g_Ah, g_Al, (base + 2 + f) * 256 + d4 * 4, v1);
            s0.x += v0.x; s0.y += v0.y; s0.z += v0.z; s0.w += v0.w;
            s1.x += v1.x; s1.y += v1.y; s1.z += v1.z; s1.w += v1.w;
        }
        const float inv = 1.0f / (float)F1N;
        split_store4(g_Ah, g_Al, base * 256 + 128 + d4 * 4,
                     make_float4((s0.x + s1.x) * inv, (s0.y + s1.y) * inv,
                                 (s0.z + s1.z) * inv, (s0.w + s1.w) * inv));
        uint2 z = make_uint2(0u, 0u);
        *reinterpret_cast<uint2*>(g_Ah + (base + 11) * 256 + d4 * 4) = z;
        *reinterpret_cast<uint2*>(g_Al + (base + 11) * 256 + d4 * 4) = z;
        *reinterpret_cast<uint2*>(g_Ah + (base + 11) * 256 + 128 + d4 * 4) = z;
        *reinterpret_cast<uint2*>(g_Al + (base + 11) * 256 + 128 + d4 * 4) = z;
    }
}

// ---------------- GEMM1 fused with pooling, 112KB smem -> 2 CTAs/SM ----------------
// BM=96, BN=256 full-N. A double-buffered (2 x 24KB), B single-buffered (64KB).
// Per chunk: commit(B_c); commit(A_{c+1}); wait_group(1) -> B_c ready, A prefetch in flight.
// smem layout: A stage s at s*24576 (AL +12288); BH at 49152; BL at 81920. Total 114688.
__global__ __launch_bounds__(384)
void gemm1_fused(const float* __restrict__ bias) {
    constexpr int SROW = 258;
    extern __shared__ char smem[];
    const uint32_t sb = smem_u32(smem);
    const int tid = threadIdx.x, wid = tid >> 5, lane = tid & 31;
    const int row0 = blockIdx.x * 96;
    const int wm = (wid >> 2) * 32;   // 0,32,64
    const int wn = (wid & 3) * 64;    // 0..192

    float acc[2][8][4];
#pragma unroll
    for (int mi = 0; mi < 2; mi++)
#pragma unroll
        for (int j = 0; j < 8; j++)
#pragma unroll
            for (int q = 0; q < 4; q++) acc[mi][j][q] = 0.f;

    auto load_A = [&](int c, int s) {
        const int kofs = c * 64;
        const uint32_t base = sb + s * 24576;
#pragma unroll
        for (int i = tid; i < 96 * 8; i += 384) {
            int r = i >> 3, cc = i & 7;
            uint32_t sw = r * 128 + ((cc ^ (r & 7)) << 4);
            size_t go = (size_t)(row0 + r) * 256 + kofs + cc * 8;
            cp16(base + sw, g_Ah + go);
            cp16(base + 12288 + sw, g_Al + go);
        }
    };
    auto load_B = [&](int c) {
        const int kofs = c * 64;
#pragma unroll
        for (int i = tid; i < 256 * 8; i += 384) {
            int r = i >> 3, cc = i & 7;
            uint32_t sw = r * 128 + ((cc ^ (r & 7)) << 4);
            size_t go = (size_t)r * 256 + kofs + cc * 8;
            cp16(sb + 49152 + sw, g_W1hT + go);
            cp16(sb + 81920 + sw, g_W1lT + go);
        }
    };

    load_A(0, 0);
    CP_COMMIT();

    for (int c = 0; c < 4; c++) {
        const int s = c & 1;
        __syncthreads();                 // prior mma done: safe to overwrite B & A stage s^1
        load_B(c);
        CP_COMMIT();
        if (c < 3) {
            load_A(c + 1, s ^ 1);
            CP_COMMIT();
            CP_WAIT(1);                  // B_c (and A_c) done; A_{c+1} may still fly
        } else {
            CP_WAIT(0);
        }
        __syncthreads();

        const uint32_t ah_b = sb + s * 24576;
        const uint32_t al_b = ah_b + 12288;
#pragma unroll
        for (int k16 = 0; k16 < 4; k16++) {
            const int cc = k16 * 2 + (lane >> 4);
            uint32_t ah[2][4], al[2][4], bh[4][4], bl[4][4];
#pragma unroll
            for (int mi = 0; mi < 2; mi++) {
                int r = wm + mi * 16 + (lane & 15);
                uint32_t ad = r * 128 + ((cc ^ (r & 7)) << 4);
                ldsm4(ah[mi], ah_b + ad);
                ldsm4(al[mi], al_b + ad);
            }
#pragma unroll
            for (int ni = 0; ni < 4; ni++) {
                int r = wn + ni * 16 + (lane & 15);
                uint32_t ad = r * 128 + ((cc ^ (r & 7)) << 4);
                ldsm4(bh[ni], sb + 49152 + ad);
                ldsm4(bl[ni], sb + 81920 + ad);
            }
#pragma unroll
            for (int mi = 0; mi < 2; mi++)
#pragma unroll
                for (int j = 0; j < 8; j++) {
                    uint32_t bfh[2] = {bh[j >> 1][j & 1], bh[j >> 1][(j & 1) + 2]};
                    uint32_t bfl[2] = {bl[j >> 1][j & 1], bl[j >> 1][(j & 1) + 2]};
                    mma16816(acc[mi][j], ah[mi], bfh);
                    mma16816(acc[mi][j], ah[mi], bfl);
                    mma16816(acc[mi][j], al[mi], bfh);
                }
        }
    }
    __syncthreads();

    // epilogue: acc (+bias, ReLU) -> smem fp32 tile [96][258] (reuses pipeline smem)
    float* sacc = reinterpret_cast<float*>(smem);
    const int g = lane >> 2, q = lane & 3;
#pragma unroll
    for (int mi = 0; mi < 2; mi++)
#pragma unroll
        for (int j = 0; j < 8; j++) {
            int ccol = wn + j * 8 + 2 * q;
            float bx = __ldg(bias + ccol);
            float by = __ldg(bias + ccol + 1);
            int r = wm + mi * 16 + g;
            sacc[r * SROW + ccol]           = fmaxf(acc[mi][j][0] + bx, 0.f);
            sacc[r * SROW + ccol + 1]       = fmaxf(acc[mi][j][1] + by, 0.f);
            sacc[(r + 8) * SROW + ccol]     = fmaxf(acc[mi][j][2] + bx, 0.f);
            sacc[(r + 8) * SROW + ccol + 1] = fmaxf(acc[mi][j][3] + by, 0.f);
        }
    __syncthreads();

    // pool: 8 groups x 128 col-pairs -> A2 = [h0 | mean(h1)] split bf16 (full 512 row)
#pragma unroll 1
    for (int i = tid; i < 8 * 128; i += 384) {
        int cp = i & 127;
        int grp = i >> 7;
        int c = cp * 2;
        int b = blockIdx.x * 8 + grp;
        const float* rowp = sacc + grp * 12 * SROW + c;
        float h0x = rowp[0], h0y = rowp[1];
        float sx = 0.f, sy = 0.f;
#pragma unroll
        for (int r = 1; r <= 10; r++) {
            sx += rowp[r * SROW];
            sy += rowp[r * SROW + 1];
        }
        size_t ob = (size_t)b * 512 + c;
        split_store2(g_A2h, g_A2l, ob, h0x, h0y);
        split_store2(g_A2h, g_A2l, ob + 256, sx * 0.1f, sy * 0.1f);
    }
}

// ---------------- GEMM2: out = A2 @ W2 + b2, 3-stage pipeline, 3 CTAs/SM ----------------
// BM=32, BN=64, K=512 (8 chunks), 128 threads (4 warps: 1M x 4N? -> 32/32=1 M, WN=16).
__global__ __launch_bounds__(128)
void gemm2_mma(const float* __restrict__ bias, float* __restrict__ C) {
    constexpr int NCH = 8;
    constexpr int SA = 32 * 128;            // 4096 per A array
    constexpr int SB = 64 * 128;            // 8192 per B array
    constexpr int STAGE = 2 * SA + 2 * SB;  // 24576
    extern __shared__ char smem[];
    const uint32_t sb = smem_u32(smem);
    const int tid = threadIdx.x, wid = tid >> 5, lane = tid & 31;
    const int row0 = blockIdx.x * 32, col0 = blockIdx.y * 64;
    const int wm = (wid >> 2) * 32;   // 0 (1 M-tile of 32)
    const int wn = (wid & 3) * 16;

    float acc[2][2][4];
#pragma unroll
    for (int mi = 0; mi < 2; mi++)
#pragma unroll
        for (int j = 0; j < 2; j++)
#pragma unroll
            for (int q = 0; q < 4; q++) acc[mi][j][q] = 0.f;

    auto load_stage = [&](int c, int s) {
        const int kofs = c * 64;
        const uint32_t base = sb + s * STAGE;
#pragma unroll
        for (int i = tid; i < 32 * 8; i += 128) {
            int r = i >> 3, cc = i & 7;
            uint32_t sw = r * 128 + ((cc ^ (r & 7)) << 4);
            size_t go = (size_t)(row0 + r) * 512 + kofs + cc * 8;
            cp16(base + sw, g_A2h + go);
            cp16(base + SA + sw, g_A2l + go);
        }
#pragma unroll
        for (int i = tid; i < 64 * 8; i += 128) {
            int r = i >> 3, cc = i & 7;
            uint32_t sw = r * 128 + ((cc ^ (r & 7)) << 4);
            size_t go = (size_t)(col0 + r) * 512 + kofs + cc * 8;
            cp16(base + 2 * SA + sw, g_W2hT + go);
            cp16(base + 2 * SA + SB + sw, g_W2lT + go);
        }
    };

    load_stage(0, 0); CP_COMMIT();
    load_stage(1, 1); CP_COMMIT();

    for (int c = 0; c < NCH; c++) {
        if (c < NCH - 1) CP_WAIT(1); else CP_WAIT(0);
        __syncthreads();
        const uint32_t base = sb + (c % 3) * STAGE;

#pragma unroll
        for (int k16 = 0; k16 < 4; k16++) {
            const int cc = k16 * 2 + (lane >> 4);
            uint32_t ah[2][4], al[2][4], bh[4], bl[4];
#pragma unroll
            for (int mi = 0; mi < 2; mi++) {
                int r = wm + mi * 16 + (lane & 15);
                uint32_t ad = base + r * 128 + ((cc ^ (r & 7)) << 4);
                ldsm4(ah[mi], ad);
                ldsm4(al[mi], ad + SA);
            }
            {
                int r = wn + (lane & 15);
                uint32_t ad = base + 2 * SA + r * 128 + ((cc ^ (r & 7)) << 4);
                ldsm4(bh, ad);
                ldsm4(bl, ad + SB);
            }
#pragma unroll
            for (int mi = 0; mi < 2; mi++)
#pragma unroll
                for (int j = 0; j < 2; j++) {
                    uint32_t bfh[2] = {bh[j], bh[j + 2]};
                    uint32_t bfl[2] = {bl[j], bl[j + 2]};
                    mma16816(acc[mi][j], ah[mi], bfh);
                    mma16816(acc[mi][j], ah[mi], bfl);
                    mma16816(acc[mi][j], al[mi], bfh);
                }
        }
        if (c + 2 < NCH) {
            load_stage(c + 2, (c + 2) % 3);
            CP_COMMIT();
        }
    }

    const int g = lane >> 2, q = lane & 3;
#pragma unroll
    for (int mi = 0; mi < 2; mi++)
#pragma unroll
        for (int j = 0; j < 2; j++) {
            int ccol = col0 + wn + j * 8 + 2 * q;
            float bx = __ldg(bias + ccol), by = __ldg(bias + ccol + 1);
            int r0 = row0 + wm + mi * 16 + g;
            float2 v0 = make_float2(acc[mi][j][0] + bx, acc[mi][j][1] + by);
            float2 v1 = make_float2(acc[mi][j][2] + bx, acc[mi][j][3] + by);
            *reinterpret_cast<float2*>(&C[(size_t)r0 * 256 + ccol]) = v0;
            *reinterpret_cast<float2*>(&C[(size_t)(r0 + 8) * 256 + ccol]) = v1;
        }
}

// ---------------- launch (single stream, 3 kernels) ----------------
static constexpr int SMEM1 = 114688;   // 112KB -> 2 CTAs/SM
static constexpr int SMEM2 = 73728;    // 3 x 24KB stages -> 3 CTAs/SM

extern "C" void kernel_launch(void* const* d_in, const int* in_sizes, int n_in,
                              void* d_out, int out_size) {
    const float* x  = (const float*)d_in[0];
    const float* W1 = (const float*)d_in[1];
    const float* b1 = (const float*)d_in[2];
    const float* W2 = (const float*)d_in[3];
    const float* b2 = (const float*)d_in[4];
    float* out = (float*)d_out;

    cudaFuncSetAttribute((const void*)gemm1_fused,
                         cudaFuncAttributeMaxDynamicSharedMemorySize, SMEM1);
    cudaFuncSetAttribute((const void*)gemm2_mma,
                         cudaFuncAttributeMaxDynamicSharedMemorySize, SMEM2);

    // K1: merged weight prep (192 blocks) + neighbor-mean reduce (2816 blocks)
    {
        int red_total = BB * F1N * D4 + BB * D4;  // 720896
        int red_blocks = (red_total + 255) / 256; // 2816
        k_prep<<<CONVW_BLOCKS + red_blocks, 256>>>(
            reinterpret_cast<const float4*>(x), W1, W2);
    }
    // GEMM1 + pooling fused, full-N: grid 256 CTAs, 2 CTAs/SM co-resident
    gemm1_fused<<<MPAD / 96, 384, SMEM1>>>(b1);
    // GEMM2: out = A2 @ W2 + b2, grid 64x4 = 256 CTAs, 3-stage pipeline
    gemm2_mma<<<dim3(BB / 32, 4), 128, SMEM2>>>(b2, out);
}

// round 11
// speedup vs baseline: 1.0181x; 1.0181x over previous
#include <cuda_runtime.h>
#include <cuda_bf16.h>
#include <cstdint>

// ---------------- problem constants ----------------
#define BB    2048
#define F1N   10
#define F2N   25
#define NTOK  261
#define D4    32
#define GRP   12                 // rows per batch group (h0 + 10*h1 + 1 dummy)
#define MPAD  (BB * GRP)         // 24576 padded GEMM1 rows

// ---------------- scratch (device globals, allocation-free) ----------------
__device__ __align__(16) __nv_bfloat16 g_Ah[MPAD * 256];
__device__ __align__(16) __nv_bfloat16 g_Al[MPAD * 256];
__device__ __align__(16) __nv_bfloat16 g_A2h[BB * 512];
__device__ __align__(16) __nv_bfloat16 g_A2l[BB * 512];
__device__ __align__(16) __nv_bfloat16 g_W1hT[256 * 256];
__device__ __align__(16) __nv_bfloat16 g_W1lT[256 * 256];
__device__ __align__(16) __nv_bfloat16 g_W2hT[256 * 512];
__device__ __align__(16) __nv_bfloat16 g_W2lT[256 * 512];

// ---------------- PTX helpers (base sm_100-safe) ----------------
__device__ __forceinline__ uint32_t smem_u32(const void* p) {
    uint32_t a;
    asm("{ .reg .u64 t; cvta.to.shared.u64 t, %1; cvt.u32.u64 %0, t; }" : "=r"(a) : "l"(p));
    return a;
}
__device__ __forceinline__ void cp16(uint32_t s, const void* g) {
    asm volatile("cp.async.cg.shared.global [%0], [%1], 16;" :: "r"(s), "l"(g));
}
#define CP_COMMIT() asm volatile("cp.async.commit_group;" ::: "memory")
#define CP_WAIT(n)  asm volatile("cp.async.wait_group %0;" :: "n"(n) : "memory")

__device__ __forceinline__ void ldsm4(uint32_t* r, uint32_t addr) {
    asm volatile("ldmatrix.sync.aligned.m8n8.x4.shared.b16 {%0,%1,%2,%3}, [%4];"
                 : "=r"(r[0]), "=r"(r[1]), "=r"(r[2]), "=r"(r[3]) : "r"(addr));
}
__device__ __forceinline__ void mma16816(float* c, const uint32_t* a, const uint32_t* b) {
    asm volatile(
        "mma.sync.aligned.m16n8k16.row.col.f32.bf16.bf16.f32 "
        "{%0,%1,%2,%3}, {%4,%5,%6,%7}, {%8,%9}, {%0,%1,%2,%3};"
        : "+f"(c[0]), "+f"(c[1]), "+f"(c[2]), "+f"(c[3])
        : "r"(a[0]), "r"(a[1]), "r"(a[2]), "r"(a[3]), "r"(b[0]), "r"(b[1]));
}

// ---------------- bf16 split helpers ----------------
__device__ __forceinline__ void split1(float w, unsigned short& h, unsigned short& l) {
    __nv_bfloat16 hb = __float2bfloat16_rn(w);
    float r = w - __bfloat162float(hb);
    __nv_bfloat16 lb = __float2bfloat16_rn(r);
    h = __bfloat16_as_ushort(hb);
    l = __bfloat16_as_ushort(lb);
}
__device__ __forceinline__ void split_store2(__nv_bfloat16* H, __nv_bfloat16* L,
                                             size_t idx, float a, float b) {
    unsigned short h0, l0, h1, l1;
    split1(a, h0, l0);
    split1(b, h1, l1);
    *reinterpret_cast<uint32_t*>(H + idx) = (uint32_t)h0 | ((uint32_t)h1 << 16);
    *reinterpret_cast<uint32_t*>(L + idx) = (uint32_t)l0 | ((uint32_t)l1 << 16);
}
__device__ __forceinline__ void split_store4(__nv_bfloat16* H, __nv_bfloat16* L,
                                             size_t idx, float4 v) {
    unsigned short hs[4], ls[4];
    float f[4] = {v.x, v.y, v.z, v.w};
#pragma unroll
    for (int i = 0; i < 4; i++) split1(f[i], hs[i], ls[i]);
    *reinterpret_cast<uint2*>(H + idx) =
        make_uint2((uint32_t)hs[0] | ((uint32_t)hs[1] << 16),
                   (uint32_t)hs[2] | ((uint32_t)hs[3] << 16));
    *reinterpret_cast<uint2*>(L + idx) =
        make_uint2((uint32_t)ls[0] | ((uint32_t)ls[1] << 16),
                   (uint32_t)ls[2] | ((uint32_t)ls[3] << 16));
}

// ---------------- K1: merged weight-prep + neighbor-mean reduce (at HBM floor) ----------------
#define CONVW_BLOCKS 192
__global__ __launch_bounds__(256)
void k_prep(const float4* __restrict__ x4,
            const float* __restrict__ W1, const float* __restrict__ W2) {
    __shared__ float tile[32][33];
    if (blockIdx.x < CONVW_BLOCKS) {
        int t = blockIdx.x;
        const float* W;
        __nv_bfloat16 *OH, *OL;
        int KD, ND, tk, tn;
        if (t < 64) {
            W = W1; OH = g_W1hT; OL = g_W1lT; KD = 256; ND = 256;
            tk = t >> 3; tn = t & 7;
        } else {
            t -= 64;
            W = W2; OH = g_W2hT; OL = g_W2lT; KD = 512; ND = 256;
            tk = t >> 3; tn = t & 7;
        }
        int x = threadIdx.x & 31, y0 = threadIdx.x >> 5;
#pragma unroll
        for (int yy = 0; yy < 4; yy++) {
            int k = tk * 32 + y0 * 4 + yy;
            tile[y0 * 4 + yy][x] = W[(size_t)k * ND + tn * 32 + x];
        }
        __syncthreads();
#pragma unroll
        for (int yy = 0; yy < 4; yy++) {
            int n = tn * 32 + y0 * 4 + yy;
            float v = tile[x][y0 * 4 + yy];
            unsigned short h, l;
            split1(v, h, l);
            size_t o = (size_t)n * KD + tk * 32 + x;
            OH[o] = __ushort_as_bfloat16(h);
            OL[o] = __ushort_as_bfloat16(l);
        }
        return;
    }

    const int HOP2_SLOTS = BB * F1N * D4;  // 655360
    int idx = (blockIdx.x - CONVW_BLOCKS) * blockDim.x + threadIdx.x;
    if (idx < HOP2_SLOTS) {
        int d4 = idx & 31;
        int fg = idx >> 5;
        int f = fg % F1N;
        int b = fg / F1N;
        const float4* p = x4 + (size_t)b * NTOK * D4 + (size_t)(1 + F1N + f * F2N) * D4 + d4;
        float4 s[5];
#pragma unroll
        for (int j = 0; j < 5; j++) s[j] = make_float4(0.f, 0.f, 0.f, 0.f);
#pragma unroll
        for (int kb = 0; kb < 5; kb++) {
#pragma unroll
            for (int j = 0; j < 5; j++) {
                float4 v = p[(size_t)(kb * 5 + j) * D4];
                s[j].x += v.x; s[j].y += v.y; s[j].z += v.z; s[j].w += v.w;
            }
        }
        float4 tot = make_float4(
            s[0].x + s[1].x + s[2].x + s[3].x + s[4].x,
            s[0].y + s[1].y + s[2].y + s[3].y + s[4].y,
            s[0].z + s[1].z + s[2].z + s[3].z + s[4].z,
            s[0].w + s[1].w + s[2].w + s[3].w + s[4].w);
        const float inv = 1.0f / (float)F2N;
        size_t row = (size_t)b * GRP + 1 + f;
        split_store4(g_Ah, g_Al, row * 256 + 128 + d4 * 4,
                     make_float4(tot.x * inv, tot.y * inv, tot.z * inv, tot.w * inv));
    } else {
        int j = idx - HOP2_SLOTS;
        if (j >= BB * D4) return;
        int d4 = j & 31;
        int b = j >> 5;
        const float4* p = x4 + (size_t)b * NTOK * D4;
        size_t base = (size_t)b * GRP;
        split_store4(g_Ah, g_Al, base * 256 + d4 * 4, p[d4]);  // seed
        float4 s0 = make_float4(0.f, 0.f, 0.f, 0.f), s1 = s0;
#pragma unroll
        for (int f = 0; f < F1N; f += 2) {
            float4 v0 = p[(size_t)(1 + f) * D4 + d4];
            float4 v1 = p[(size_t)(2 + f) * D4 + d4];
            split_store4(g_Ah, g_Al, (base + 1 + f) * 256 + d4 * 4, v0);
            split_store4(g_Ah, g_Al, (base + 2 + f) * 256 + d4 * 4, v1);
            s0.x += v0.x; s0.y += v0.y; s0.z += v0.z; s0.w += v0.w;
            s1.x += v1.x; s1.y += v1.y; s1.z += v1.z; s1.w += v1.w;
        }
        const float inv = 1.0f / (float)F1N;
        split_store4(g_Ah, g_Al, base * 256 + 128 + d4 * 4,
                     make_float4((s0.x + s1.x) * inv, (s0.y + s1.y) * inv,
                                 (s0.z + s1.z) * inv, (s0.w + s1.w) * inv));
        uint2 z = make_uint2(0u, 0u);
        *reinterpret_cast<uint2*>(g_Ah + (base + 11) * 256 + d4 * 4) = z;
        *reinterpret_cast<uint2*>(g_Al + (base + 11) * 256 + d4 * 4) = z;
        *reinterpret_cast<uint2*>(g_Ah + (base + 11) * 256 + 128 + d4 * 4) = z;
        *reinterpret_cast<uint2*>(g_Al + (base + 11) * 256 + 128 + d4 * 4) = z;
    }
}

// ---------------- GEMM1 fused with pooling, 112KB smem -> 2 CTAs/SM ----------------
// BM=96, BN=256 full-N. A double-buffered (2 x 24KB), B single-buffered (64KB).
__global__ __launch_bounds__(384)
void gemm1_fused(const float* __restrict__ bias) {
    constexpr int SROW = 258;
    extern __shared__ char smem[];
    const uint32_t sb = smem_u32(smem);
    const int tid = threadIdx.x, wid = tid >> 5, lane = tid & 31;
    const int row0 = blockIdx.x * 96;
    const int wm = (wid >> 2) * 32;   // 0,32,64
    const int wn = (wid & 3) * 64;    // 0..192

    float acc[2][8][4];
#pragma unroll
    for (int mi = 0; mi < 2; mi++)
#pragma unroll
        for (int j = 0; j < 8; j++)
#pragma unroll
            for (int q = 0; q < 4; q++) acc[mi][j][q] = 0.f;

    auto load_A = [&](int c, int s) {
        const int kofs = c * 64;
        const uint32_t base = sb + s * 24576;
#pragma unroll
        for (int i = tid; i < 96 * 8; i += 384) {
            int r = i >> 3, cc = i & 7;
            uint32_t sw = r * 128 + ((cc ^ (r & 7)) << 4);
            size_t go = (size_t)(row0 + r) * 256 + kofs + cc * 8;
            cp16(base + sw, g_Ah + go);
            cp16(base + 12288 + sw, g_Al + go);
        }
    };
    auto load_B = [&](int c) {
        const int kofs = c * 64;
#pragma unroll
        for (int i = tid; i < 256 * 8; i += 384) {
            int r = i >> 3, cc = i & 7;
            uint32_t sw = r * 128 + ((cc ^ (r & 7)) << 4);
            size_t go = (size_t)r * 256 + kofs + cc * 8;
            cp16(sb + 49152 + sw, g_W1hT + go);
            cp16(sb + 81920 + sw, g_W1lT + go);
        }
    };

    load_A(0, 0);
    CP_COMMIT();

    for (int c = 0; c < 4; c++) {
        const int s = c & 1;
        __syncthreads();                 // prior mma done: safe to overwrite B & A stage s^1
        load_B(c);
        CP_COMMIT();
        if (c < 3) {
            load_A(c + 1, s ^ 1);
            CP_COMMIT();
            CP_WAIT(1);                  // B_c (and A_c) done; A_{c+1} may still fly
        } else {
            CP_WAIT(0);
        }
        __syncthreads();

        const uint32_t ah_b = sb + s * 24576;
        const uint32_t al_b = ah_b + 12288;
#pragma unroll
        for (int k16 = 0; k16 < 4; k16++) {
            const int cc = k16 * 2 + (lane >> 4);
            uint32_t ah[2][4], al[2][4], bh[4][4], bl[4][4];
#pragma unroll
            for (int mi = 0; mi < 2; mi++) {
                int r = wm + mi * 16 + (lane & 15);
                uint32_t ad = r * 128 + ((cc ^ (r & 7)) << 4);
                ldsm4(ah[mi], ah_b + ad);
                ldsm4(al[mi], al_b + ad);
            }
#pragma unroll
            for (int ni = 0; ni < 4; ni++) {
                int r = wn + ni * 16 + (lane & 15);
                uint32_t ad = r * 128 + ((cc ^ (r & 7)) << 4);
                ldsm4(bh[ni], sb + 49152 + ad);
                ldsm4(bl[ni], sb + 81920 + ad);
            }
#pragma unroll
            for (int mi = 0; mi < 2; mi++)
#pragma unroll
                for (int j = 0; j < 8; j++) {
                    uint32_t bfh[2] = {bh[j >> 1][j & 1], bh[j >> 1][(j & 1) + 2]};
                    uint32_t bfl[2] = {bl[j >> 1][j & 1], bl[j >> 1][(j & 1) + 2]};
                    mma16816(acc[mi][j], ah[mi], bfh);
                    mma16816(acc[mi][j], ah[mi], bfl);
                    mma16816(acc[mi][j], al[mi], bfh);
                }
        }
    }
    __syncthreads();

    // epilogue: acc (+bias, ReLU) -> smem fp32 tile [96][258]
    float* sacc = reinterpret_cast<float*>(smem);
    const int g = lane >> 2, q = lane & 3;
#pragma unroll
    for (int mi = 0; mi < 2; mi++)
#pragma unroll
        for (int j = 0; j < 8; j++) {
            int ccol = wn + j * 8 + 2 * q;
            float bx = __ldg(bias + ccol);
            float by = __ldg(bias + ccol + 1);
            int r = wm + mi * 16 + g;
            sacc[r * SROW + ccol]           = fmaxf(acc[mi][j][0] + bx, 0.f);
            sacc[r * SROW + ccol + 1]       = fmaxf(acc[mi][j][1] + by, 0.f);
            sacc[(r + 8) * SROW + ccol]     = fmaxf(acc[mi][j][2] + bx, 0.f);
            sacc[(r + 8) * SROW + ccol + 1] = fmaxf(acc[mi][j][3] + by, 0.f);
        }
    __syncthreads();

    // pool: 8 groups x 128 col-pairs -> A2 = [h0 | mean(h1)] split bf16 (full 512 row)
#pragma unroll 1
    for (int i = tid; i < 8 * 128; i += 384) {
        int cp = i & 127;
        int grp = i >> 7;
        int c = cp * 2;
        int b = blockIdx.x * 8 + grp;
        const float* rowp = sacc + grp * 12 * SROW + c;
        float h0x = rowp[0], h0y = rowp[1];
        float sx = 0.f, sy = 0.f;
#pragma unroll
        for (int r = 1; r <= 10; r++) {
            sx += rowp[r * SROW];
            sy += rowp[r * SROW + 1];
        }
        size_t ob = (size_t)b * 512 + c;
        split_store2(g_A2h, g_A2l, ob, h0x, h0y);
        split_store2(g_A2h, g_A2l, ob + 256, sx * 0.1f, sy * 0.1f);
    }
}

// ---------------- GEMM2: out = A2 @ W2 + b2 (round-4/9 measured-11.6us shape) ----------------
template <int BM, int BN, int KTOT, int WM, int WN>
__global__ __launch_bounds__((BM / WM) * (BN / WN) * 32)
void gemm_mma(const __nv_bfloat16* __restrict__ Ah_g, const __nv_bfloat16* __restrict__ Al_g,
              const __nv_bfloat16* __restrict__ Bh_g, const __nv_bfloat16* __restrict__ Bl_g,
              const float* __restrict__ bias, float* __restrict__ C) {
    constexpr int NTH = (BM / WM) * (BN / WN) * 32;
    constexpr int NCH = KTOT / 64;
    constexpr int SA = BM * 128;
    constexpr int SB = BN * 128;
    constexpr int STAGE = 2 * SA + 2 * SB;
    constexpr int NWN = BN / WN;
    constexpr int MT = WM / 16;
    constexpr int NT8 = WN / 8;
    constexpr int NT16 = WN / 16;

    extern __shared__ char smem[];
    const uint32_t sb = smem_u32(smem);
    const int tid = threadIdx.x, wid = tid >> 5, lane = tid & 31;
    const int row0 = blockIdx.x * BM, col0 = blockIdx.y * BN;
    const int wm = (wid / NWN) * WM;
    const int wn = (wid % NWN) * WN;

    float acc[MT][NT8][4];
#pragma unroll
    for (int mi = 0; mi < MT; mi++)
#pragma unroll
        for (int j = 0; j < NT8; j++)
#pragma unroll
            for (int q = 0; q < 4; q++) acc[mi][j][q] = 0.f;

    auto load_stage = [&](int c, int s) {
        const int kofs = c * 64;
        const uint32_t base = sb + s * STAGE;
#pragma unroll
        for (int i = tid; i < BM * 8; i += NTH) {
            int r = i >> 3, cc = i & 7;
            uint32_t sw = r * 128 + ((cc ^ (r & 7)) << 4);
            size_t go = (size_t)(row0 + r) * KTOT + kofs + cc * 8;
            cp16(base + sw, Ah_g + go);
            cp16(base + SA + sw, Al_g + go);
        }
#pragma unroll
        for (int i = tid; i < BN * 8; i += NTH) {
            int r = i >> 3, cc = i & 7;
            uint32_t sw = r * 128 + ((cc ^ (r & 7)) << 4);
            size_t go = (size_t)(col0 + r) * KTOT + kofs + cc * 8;
            cp16(base + 2 * SA + sw, Bh_g + go);
            cp16(base + 2 * SA + SB + sw, Bl_g + go);
        }
    };

    load_stage(0, 0);
    CP_COMMIT();

    for (int c = 0; c < NCH; c++) {
        const int s = c & 1;
        if (c + 1 < NCH) {
            load_stage(c + 1, s ^ 1);
            CP_COMMIT();
            CP_WAIT(1);
        } else {
            CP_WAIT(0);
        }
        __syncthreads();
        const uint32_t base = sb + s * STAGE;

#pragma unroll
        for (int k16 = 0; k16 < 4; k16++) {
            const int cc = k16 * 2 + (lane >> 4);
            uint32_t ah[MT][4], al[MT][4], bh[NT16][4], bl[NT16][4];
#pragma unroll
            for (int mi = 0; mi < MT; mi++) {
                int r = wm + mi * 16 + (lane & 15);
                uint32_t ad = base + r * 128 + ((cc ^ (r & 7)) << 4);
                ldsm4(ah[mi], ad);
                ldsm4(al[mi], ad + SA);
            }
#pragma unroll
            for (int ni = 0; ni < NT16; ni++) {
                int r = wn + ni * 16 + (lane & 15);
                uint32_t ad = base + 2 * SA + r * 128 + ((cc ^ (r & 7)) << 4);
                ldsm4(bh[ni], ad);
                ldsm4(bl[ni], ad + SB);
            }
#pragma unroll
            for (int mi = 0; mi < MT; mi++)
#pragma unroll
                for (int j = 0; j < NT8; j++) {
                    uint32_t bfh[2] = {bh[j >> 1][j & 1], bh[j >> 1][(j & 1) + 2]};
                    uint32_t bfl[2] = {bl[j >> 1][j & 1], bl[j >> 1][(j & 1) + 2]};
                    mma16816(acc[mi][j], ah[mi], bfh);
                    mma16816(acc[mi][j], ah[mi], bfl);
                    mma16816(acc[mi][j], al[mi], bfh);
                }
        }
        __syncthreads();
    }

    const int g = lane >> 2, q = lane & 3;
#pragma unroll
    for (int mi = 0; mi < MT; mi++)
#pragma unroll
        for (int j = 0; j < NT8; j++) {
            int ccol = col0 + wn + j * 8 + 2 * q;
            float bx = __ldg(bias + ccol), by = __ldg(bias + ccol + 1);
            int r0 = row0 + wm + mi * 16 + g;
            float2 v0 = make_float2(acc[mi][j][0] + bx, acc[mi][j][1] + by);
            float2 v1 = make_float2(acc[mi][j][2] + bx, acc[mi][j][3] + by);
            *reinterpret_cast<float2*>(&C[(size_t)r0 * 256 + ccol]) = v0;
            *reinterpret_cast<float2*>(&C[(size_t)(r0 + 8) * 256 + ccol]) = v1;
        }
}

// ---------------- launch (single stream, 3 kernels) ----------------
static constexpr int SMEM1 = 114688;   // 112KB -> 2 CTAs/SM
static constexpr int SMEM2 = 2 * (2 * 64 * 128 + 2 * 64 * 128);   // 65536

extern "C" void kernel_launch(void* const* d_in, const int* in_sizes, int n_in,
                              void* d_out, int out_size) {
    const float* x  = (const float*)d_in[0];
    const float* W1 = (const float*)d_in[1];
    const float* b1 = (const float*)d_in[2];
    const float* W2 = (const float*)d_in[3];
    const float* b2 = (const float*)d_in[4];
    float* out = (float*)d_out;

    __nv_bfloat16 *a2h, *a2l, *w2h, *w2l;
    cudaGetSymbolAddress((void**)&a2h, g_A2h);
    cudaGetSymbolAddress((void**)&a2l, g_A2l);
    cudaGetSymbolAddress((void**)&w2h, g_W2hT);
    cudaGetSymbolAddress((void**)&w2l, g_W2lT);

    cudaFuncSetAttribute((const void*)gemm1_fused,
                         cudaFuncAttributeMaxDynamicSharedMemorySize, SMEM1);
    cudaFuncSetAttribute((const void*)gemm_mma<64, 64, 512, 32, 16>,
                         cudaFuncAttributeMaxDynamicSharedMemorySize, SMEM2);

    // K1: merged weight prep (192 blocks) + neighbor-mean reduce (2816 blocks)
    {
        int red_total = BB * F1N * D4 + BB * D4;  // 720896
        int red_blocks = (red_total + 255) / 256; // 2816
        k_prep<<<CONVW_BLOCKS + red_blocks, 256>>>(
            reinterpret_cast<const float4*>(x), W1, W2);
    }
    // GEMM1 + pooling fused, full-N: grid 256 CTAs, 2 CTAs/SM co-resident
    gemm1_fused<<<MPAD / 96, 384, SMEM1>>>(b1);
    // GEMM2: out = A2 @ W2 + b2, grid 32x4, 256 thr (measured 11.6us shape)
    gemm_mma<64, 64, 512, 32, 16>
        <<<dim3(BB / 64, 4), 256, SMEM2>>>(a2h, a2l, w2h, w2l, b2, out);
}